// round 7
// baseline (speedup 1.0000x reference)
#include <cuda_runtime.h>

#define NB 16            // batch
#define NS 65            // segments per batch
#define NR 1040          // NB*NS rows
#define NW 256           // candidate positions per row
#define ND 128           // feature dim
#define T_PAD 2176       // padded time length of x
#define LSEQ 2048        // MAX_LEN_SEQ
#define MIN_SEG 32
#define NOUT (NB * LSEQ) // 32768 output rows
#define SENT 0xFFFFFFFFu
#define FULL 0xffffffffu

#define EXP_BLOCKS 130
#define FILL_BLOCKS 30

__device__ int  g_offset[NR];   // per-row source base offset within batch
__device__ int  g_pre[NR];      // in-batch exclusive prefix of counts
__device__ int  g_cnt[NR];      // per-row masked count
__device__ int  g_S[NB];        // per-batch total count
__device__ uint2 g_entry[NOUT]; // .x = base|(w<<16), .y = scale bits; SENT = zero

// Exact-boundary row count: smallest w in [0,NW] with floor(rn(w/sc)) >= Tm.
// w* lies within +-3 of Tm*sc; probe an 8-wide window with INDEPENDENT IEEE
// divides using the reference's exact predicate.
__device__ __forceinline__ int row_count(int Tm, float sc) {
    if (Tm <= 0) return 0;
    float wr = (float)Tm * sc;
    int wlo = (int)wr - 3;
    if (wlo < 0) wlo = 0;
    if (wlo >= NW) return NW;
    float fT = (float)Tm;
    int cnt = NW;
    #pragma unroll
    for (int j = 0; j < 8; j++) {
        int w = wlo + j;
        bool fail = (w < NW) && (floorf(__fdiv_rn((float)w, sc)) >= fT);
        if (fail && w < cnt) cnt = w;   // ascending -> min = first fail
    }
    return cnt;
}

// 65-element exclusive shfl-scan helper (warp 0 only), vals in shared.
__device__ __forceinline__ void warp_excl_scan65(int* v, int lane) {
    int carry = 0;
    #pragma unroll
    for (int c = 0; c < 3; c++) {
        int i = c * 32 + lane;
        int x = (i < NS) ? v[i] : 0;
        int s = x;
        #pragma unroll
        for (int o = 1; o < 32; o <<= 1) {
            int u = __shfl_up_sync(FULL, s, o);
            if (lane >= o) s += u;
        }
        if (i < NS) v[i] = carry + s - x;     // exclusive
        carry += __shfl_sync(FULL, s, 31);
    }
    // after: v[] holds exclusive prefix; total = carry (lane-uniform in warp 0)
    if (lane == 0) v[NS] = carry;             // stash total at [NS]
}

// ---------------------------------------------------------------------------
// Setup: one block per batch. Segment cumsum, per-row counts, in-batch prefix.
// ---------------------------------------------------------------------------
__global__ void __launch_bounds__(128)
setup_kernel(const float* __restrict__ scales,
             const int* __restrict__ len_seq,
             const int* __restrict__ len_seg_raw) {
    __shared__ int sh_seg[NS];
    __shared__ int sh_off[NS + 1];
    __shared__ int sh_cnt[NS + 1];
    int b    = blockIdx.x;
    int tid  = threadIdx.x;
    int lane = tid & 31;
    int wid  = tid >> 5;

    if (tid < NS) sh_seg[tid] = len_seg_raw[b * NS + tid] + MIN_SEG;
    __syncthreads();

    if (wid == 0) {                    // exclusive cumsum of seg lengths
        if (lane == 0) { }             // copy into off then scan
        for (int i = lane; i < NS; i += 32) sh_off[i] = sh_seg[i];
        __syncwarp();
        warp_excl_scan65(sh_off, lane);
    }
    __syncthreads();

    int lseq = len_seq[b];
    if (tid < NS) {
        int r  = b * NS + tid;
        int Tm = min(sh_seg[tid] - 1, lseq - 1 - sh_off[tid]);
        int c  = row_count(Tm, scales[r] + 0.5f);
        sh_cnt[tid] = c;
        g_cnt[r]    = c;
        g_offset[r] = sh_off[tid];
    }
    __syncthreads();

    if (wid == 0) warp_excl_scan65(sh_cnt, lane);
    __syncthreads();

    if (tid < NS) g_pre[b * NS + tid] = sh_cnt[tid];
    if (tid == 0) g_S[b] = sh_cnt[NS];
}

// Per-block: derive batch bases (exclusive scan of g_S) + L. Lanes 0..15.
__device__ __forceinline__ void batch_bases(int* sh_base /*[NB+1]*/) {
    int lane = threadIdx.x & 31;
    if ((threadIdx.x >> 5) == 0) {
        int v = (lane < NB) ? g_S[lane] : 0;
        int s = v;
        #pragma unroll
        for (int o = 1; o < 32; o <<= 1) {
            int u = __shfl_up_sync(FULL, s, o);
            if (lane >= o) s += u;
        }
        if (lane < NB) sh_base[lane] = s - v;   // exclusive
        if (lane == NB - 1) sh_base[NB] = s;    // total
    }
    __syncthreads();
}

// ---------------------------------------------------------------------------
// Expand: blocks [0,130): warp-per-row run expansion; [130,160): sentinel fill.
// ---------------------------------------------------------------------------
__global__ void __launch_bounds__(256)
expand_kernel(const float* __restrict__ scales) {
#if __CUDA_ARCH__ >= 900
    cudaGridDependencySynchronize();
#endif
    __shared__ int sh_base[NB + 1];
    batch_bases(sh_base);
    int total = sh_base[NB];
    int L = total / NB;
    if (L <= 0) L = 1;                 // degenerate guard (bo>=NB filters writes)

    if (blockIdx.x < EXP_BLOCKS) {
        int r = (blockIdx.x * 256 + threadIdx.x) >> 5;
        int lane = threadIdx.x & 31;
        if (r >= NR) return;
        int cnt = g_cnt[r];
        if (cnt == 0) return;
        int g0   = sh_base[r / NS] + g_pre[r];
        int base = (r / NS) * T_PAD + g_offset[r];
        uint2 ev;
        ev.y = __float_as_uint(scales[r] + 0.5f);
        for (int k = lane; k < cnt; k += 32) {
            int g  = g0 + k;
            int bo = g / L;
            int t  = g - bo * L;
            if (bo < NB && t < LSEQ) {
                ev.x = (unsigned)base | ((unsigned)k << 16);
                g_entry[bo * LSEQ + t] = ev;
            }
        }
    } else {
        uint2 sent; sent.x = SENT; sent.y = 0;
        int i0 = (blockIdx.x - EXP_BLOCKS) * 256 + threadIdx.x;
        for (int i = i0; i < NOUT; i += FILL_BLOCKS * 256) {
            int t = i & (LSEQ - 1);
            if (t >= L) g_entry[i] = sent;
        }
    }
}

// ---------------------------------------------------------------------------
// Gather: two output rows per warp; one 16B descriptor load; four independent
// 512B row loads; streaming stores.
// ---------------------------------------------------------------------------
__global__ void __launch_bounds__(256)
gather_kernel(const float* __restrict__ x, float* __restrict__ out) {
#if __CUDA_ARCH__ >= 900
    cudaGridDependencySynchronize();
#endif
    int warp = (blockIdx.x * blockDim.x + threadIdx.x) >> 5;
    int lane = threadIdx.x & 31;
    int gid0 = warp << 1;
    if (gid0 >= NOUT) return;

    uint4 ee = __ldg((const uint4*)(g_entry + gid0));
    bool v0 = (ee.x != SENT);
    bool v1 = (ee.z != SENT);

    float4 a0, c0, a1, c1;
    float lam0 = 0.f, lam1 = 0.f;
    if (v0) {
        int base = (int)(ee.x & 0xFFFFu), w = (int)(ee.x >> 16);
        float fs = __fdiv_rn((float)w, __uint_as_float(ee.y));
        float fl = floorf(fs); lam0 = fs - fl;
        const float4* p = (const float4*)(x + (size_t)(base + (int)fl) * ND);
        a0 = p[lane]; c0 = p[lane + 32];
    }
    if (v1) {
        int base = (int)(ee.z & 0xFFFFu), w = (int)(ee.z >> 16);
        float fs = __fdiv_rn((float)w, __uint_as_float(ee.w));
        float fl = floorf(fs); lam1 = fs - fl;
        const float4* p = (const float4*)(x + (size_t)(base + (int)fl) * ND);
        a1 = p[lane]; c1 = p[lane + 32];
    }

    float4 y0 = make_float4(0.f, 0.f, 0.f, 0.f);
    float4 y1 = y0;
    if (v0) {
        float om = 1.0f - lam0;
        y0.x = om * a0.x + lam0 * c0.x;  y0.y = om * a0.y + lam0 * c0.y;
        y0.z = om * a0.z + lam0 * c0.z;  y0.w = om * a0.w + lam0 * c0.w;
    }
    if (v1) {
        float om = 1.0f - lam1;
        y1.x = om * a1.x + lam1 * c1.x;  y1.y = om * a1.y + lam1 * c1.y;
        y1.z = om * a1.z + lam1 * c1.z;  y1.w = om * a1.w + lam1 * c1.w;
    }
    __stcs((float4*)(out + (size_t)gid0 * ND) + lane,       y0);
    __stcs((float4*)(out + (size_t)(gid0 + 1) * ND) + lane, y1);
}

static inline void launch_pdl(void* fn, dim3 grid, dim3 block, void** args) {
    cudaLaunchConfig_t cfg = {};
    cfg.gridDim = grid;
    cfg.blockDim = block;
    cfg.dynamicSmemBytes = 0;
    cfg.stream = 0;
    cudaLaunchAttribute attr[1];
    attr[0].id = cudaLaunchAttributeProgrammaticStreamSerialization;
    attr[0].val.programmaticStreamSerializationAllowed = 1;
    cfg.attrs = attr;
    cfg.numAttrs = 1;
    cudaLaunchKernelExC(&cfg, fn, args);
}

extern "C" void kernel_launch(void* const* d_in, const int* in_sizes, int n_in,
                              void* d_out, int out_size) {
    const float* x           = (const float*)d_in[0];
    const float* scales      = (const float*)d_in[1];
    const int*   len_seq     = (const int*)d_in[2];
    const int*   len_seg_raw = (const int*)d_in[3];
    float* out = (float*)d_out;

    setup_kernel<<<NB, 128>>>(scales, len_seq, len_seg_raw);

    {
        void* args[] = { (void*)&scales };
        launch_pdl((void*)expand_kernel,
                   dim3(EXP_BLOCKS + FILL_BLOCKS), dim3(256), args);
    }
    {
        void* args[] = { (void*)&x, (void*)&out };
        launch_pdl((void*)gather_kernel, dim3(NOUT / 2 / 8), dim3(256), args);
    }
}

// round 8
// speedup vs baseline: 1.1422x; 1.1422x over previous
#include <cuda_runtime.h>

#define NB 16            // batch
#define NS 65            // segments per batch
#define NR 1040          // NB*NS rows
#define NW 256           // candidate positions per row
#define ND 128           // feature dim
#define T_PAD 2176       // padded time length of x
#define LSEQ 2048        // MAX_LEN_SEQ
#define MIN_SEG 32
#define NOUT (NB * LSEQ) // 32768 output rows
#define SENT 0xFFFFFFFFu
#define FULL 0xffffffffu

#define EXP_BLOCKS 130
#define FILL_BLOCKS 30

__device__ int  g_rowstart[NR + 1];
__device__ int  g_offset[NR];
__device__ int  g_L[1];
__device__ uint2 g_entry[NOUT];   // .x = base|(w<<16), .y = scale bits; SENT = zero row

// Exact-boundary row count: smallest w in [0,NW] with floor(rn(w/sc)) >= Tm.
// w* lies within +-3 of Tm*sc; probe an 8-wide window with INDEPENDENT IEEE
// divides using the reference's exact predicate.
__device__ __forceinline__ int row_count(int Tm, float sc) {
    if (Tm <= 0) return 0;
    float wr = (float)Tm * sc;
    int wlo = (int)wr - 3;
    if (wlo < 0) wlo = 0;
    if (wlo >= NW) return NW;
    float fT = (float)Tm;
    int cnt = NW;
    #pragma unroll
    for (int j = 0; j < 8; j++) {
        int w = wlo + j;
        bool fail = (w < NW) && (floorf(__fdiv_rn((float)w, sc)) >= fT);
        if (fail && w < cnt) cnt = w;   // ascending -> min = first fail
    }
    return cnt;
}

// ---------------------------------------------------------------------------
// Setup: per-batch segment-offset warp-scans, per-row count (window probe),
// block exclusive scan via shfl. Single block, 1024 threads. (R6 version —
// best measured wall-clock config.)
// ---------------------------------------------------------------------------
__global__ void __launch_bounds__(1024)
setup_kernel(const float* __restrict__ scales,
             const int* __restrict__ len_seq,
             const int* __restrict__ len_seg_raw) {
    __shared__ int sh_seg[NR];
    __shared__ int sh_off[NR];
    __shared__ int sh_ws[32];
    int tid  = threadIdx.x;
    int wid  = tid >> 5;
    int lane = tid & 31;

    for (int i = tid; i < NR; i += 1024) sh_seg[i] = len_seg_raw[i] + MIN_SEG;
    __syncthreads();

    if (wid < NB) {      // warp wb scans batch wb (65 elems, 3 chunks)
        int base = wid * NS;
        int carry = 0;
        #pragma unroll
        for (int c = 0; c < 3; c++) {
            int i = c * 32 + lane;
            int v = (i < NS) ? sh_seg[base + i] : 0;
            int s = v;
            #pragma unroll
            for (int o = 1; o < 32; o <<= 1) {
                int u = __shfl_up_sync(FULL, s, o);
                if (lane >= o) s += u;
            }
            if (i < NS) sh_off[base + i] = carry + s - v;   // exclusive
            carry += __shfl_sync(FULL, s, 31);
        }
    }
    __syncthreads();

    int a0 = 0, a1 = 0;
    int i0 = 2 * tid, i1 = 2 * tid + 1;
    if (i0 < NR) {
        int b = i0 / NS;
        a0 = row_count(min(sh_seg[i0] - 1, len_seq[b] - 1 - sh_off[i0]),
                       scales[i0] + 0.5f);
    }
    if (i1 < NR) {
        int b = i1 / NS;
        a1 = row_count(min(sh_seg[i1] - 1, len_seq[b] - 1 - sh_off[i1]),
                       scales[i1] + 0.5f);
    }

    int s = a0 + a1;
    int incl = s;
    #pragma unroll
    for (int o = 1; o < 32; o <<= 1) {
        int u = __shfl_up_sync(FULL, incl, o);
        if (lane >= o) incl += u;
    }
    if (lane == 31) sh_ws[wid] = incl;
    __syncthreads();
    if (wid == 0) {
        int ws = sh_ws[lane];
        #pragma unroll
        for (int o = 1; o < 32; o <<= 1) {
            int u = __shfl_up_sync(FULL, ws, o);
            if (lane >= o) ws += u;
        }
        sh_ws[lane] = ws;
    }
    __syncthreads();
    int warp_base = (wid > 0) ? sh_ws[wid - 1] : 0;
    incl += warp_base;
    int excl = incl - s;

    if (i0 < NR) { g_rowstart[i0] = excl;      g_offset[i0] = sh_off[i0]; }
    if (i1 < NR) { g_rowstart[i1] = excl + a0; g_offset[i1] = sh_off[i1]; }
    if (tid == 519) {                   // rows 1038,1039 -> incl = total
        g_rowstart[NR] = incl;
        g_L[0] = incl / NB;
    }
}

// ---------------------------------------------------------------------------
// Expand: grid-wide table build. Blocks [0,130): warp-per-segment-row run
// expansion. Blocks [130,160): sentinel fill for t >= L (disjoint entries).
// ---------------------------------------------------------------------------
__global__ void __launch_bounds__(256)
expand_kernel(const float* __restrict__ scales) {
#if __CUDA_ARCH__ >= 900
    cudaGridDependencySynchronize();
#endif
    int L = g_L[0];
    if (blockIdx.x < EXP_BLOCKS) {
        int r = (blockIdx.x * 256 + threadIdx.x) >> 5;
        int lane = threadIdx.x & 31;
        if (r >= NR) return;
        int g0  = g_rowstart[r];
        int cnt = g_rowstart[r + 1] - g0;
        if (cnt == 0) return;
        int base = (r / NS) * T_PAD + g_offset[r];
        uint2 ev;
        ev.y = __float_as_uint(scales[r] + 0.5f);
        for (int k = lane; k < cnt; k += 32) {
            int g  = g0 + k;
            int bo = g / L;
            int t  = g - bo * L;
            if (bo < NB && t < LSEQ) {
                ev.x = (unsigned)base | ((unsigned)k << 16);
                g_entry[bo * LSEQ + t] = ev;
            }
        }
    } else {
        uint2 sent; sent.x = SENT; sent.y = 0;
        int i0 = (blockIdx.x - EXP_BLOCKS) * 256 + threadIdx.x;
        for (int i = i0; i < NOUT; i += FILL_BLOCKS * 256) {
            int t = i & (LSEQ - 1);
            if (t >= L) g_entry[i] = sent;
        }
    }
}

// ---------------------------------------------------------------------------
// Gather: FOUR output rows per warp. Two 16B descriptor loads, then all eight
// independent 512B x-row loads in flight before any math. Streaming stores.
// ---------------------------------------------------------------------------
__global__ void __launch_bounds__(256)
gather_kernel(const float* __restrict__ x, float* __restrict__ out) {
#if __CUDA_ARCH__ >= 900
    cudaGridDependencySynchronize();
#endif
    int warp = (blockIdx.x * blockDim.x + threadIdx.x) >> 5;
    int lane = threadIdx.x & 31;
    int gid0 = warp << 2;              // 4 rows per warp, 32B-aligned descs
    if (gid0 >= NOUT) return;

    const uint4* ep = (const uint4*)(g_entry + gid0);
    uint4 e01 = __ldg(ep);
    uint4 e23 = __ldg(ep + 1);
    unsigned ex[4] = { e01.x, e01.z, e23.x, e23.z };
    unsigned ey[4] = { e01.y, e01.w, e23.y, e23.w };

    bool v[4];
    float lam[4];
    const float4* p[4];
    #pragma unroll
    for (int j = 0; j < 4; j++) {
        v[j] = (ex[j] != SENT);
        lam[j] = 0.f;
        p[j] = (const float4*)x;
        if (v[j]) {
            int base = (int)(ex[j] & 0xFFFFu), w = (int)(ex[j] >> 16);
            float fs = __fdiv_rn((float)w, __uint_as_float(ey[j]));
            float fl = floorf(fs);
            lam[j] = fs - fl;
            p[j] = (const float4*)(x + (size_t)(base + (int)fl) * ND);
        }
    }

    // issue all loads before any consumption (8 independent LDG.128)
    float4 a[4], c[4];
    #pragma unroll
    for (int j = 0; j < 4; j++) {
        if (v[j]) { a[j] = p[j][lane]; c[j] = p[j][lane + 32]; }
    }

    #pragma unroll
    for (int j = 0; j < 4; j++) {
        float4 y = make_float4(0.f, 0.f, 0.f, 0.f);
        if (v[j]) {
            float om = 1.0f - lam[j];
            y.x = om * a[j].x + lam[j] * c[j].x;
            y.y = om * a[j].y + lam[j] * c[j].y;
            y.z = om * a[j].z + lam[j] * c[j].z;
            y.w = om * a[j].w + lam[j] * c[j].w;
        }
        __stcs((float4*)(out + (size_t)(gid0 + j) * ND) + lane, y);
    }
}

static inline void launch_pdl(void* fn, dim3 grid, dim3 block, void** args) {
    cudaLaunchConfig_t cfg = {};
    cfg.gridDim = grid;
    cfg.blockDim = block;
    cfg.dynamicSmemBytes = 0;
    cfg.stream = 0;
    cudaLaunchAttribute attr[1];
    attr[0].id = cudaLaunchAttributeProgrammaticStreamSerialization;
    attr[0].val.programmaticStreamSerializationAllowed = 1;
    cfg.attrs = attr;
    cfg.numAttrs = 1;
    cudaLaunchKernelExC(&cfg, fn, args);
}

extern "C" void kernel_launch(void* const* d_in, const int* in_sizes, int n_in,
                              void* d_out, int out_size) {
    const float* x           = (const float*)d_in[0];
    const float* scales      = (const float*)d_in[1];
    const int*   len_seq     = (const int*)d_in[2];
    const int*   len_seg_raw = (const int*)d_in[3];
    float* out = (float*)d_out;

    setup_kernel<<<1, 1024>>>(scales, len_seq, len_seg_raw);

    {
        void* args[] = { (void*)&scales };
        launch_pdl((void*)expand_kernel,
                   dim3(EXP_BLOCKS + FILL_BLOCKS), dim3(256), args);
    }
    {
        void* args[] = { (void*)&x, (void*)&out };
        launch_pdl((void*)gather_kernel, dim3(NOUT / 4 / 8), dim3(256), args);
    }
}